// round 12
// baseline (speedup 1.0000x reference)
#include <cuda_runtime.h>
#include <cuda_bf16.h>
#include <cstdint>

#define N_NODES 100000
#define N_EDGES 1600000
#define D 64
#define N_GRAPHS 16
#define N_CLASSES 6
#define BN_EPS 1e-5f
#define MAXDEG 64   // Poisson(16): max over 100K nodes ~35; P(any >= 64) < 1e-15

#define NPB 128

// ---------------- device scratch (no allocation allowed) ----------------
__device__ __align__(16) float g_h[2][N_NODES * D];   // ping-pong layer buffers
__device__ __align__(16) float g_z[N_NODES * D];      // gathered z = h + sum h_j
__device__ int g_deg[N_NODES];                        // per-dst degree (atomic cursor)
__device__ __align__(16) int g_srcs[N_NODES * MAXDEG]; // padded CSR (16B-aligned rows)
__device__ float g_pool[N_GRAPHS * D];                // per-graph sums
__device__ float g_cnt[N_GRAPHS];                     // per-graph counts

// ---------------- packed f32x2 helpers (FFMA2: 2x FP32 FMA rate) ----------
__device__ __forceinline__ void unpack2(float& lo, float& hi, unsigned long long v) {
    asm("mov.b64 {%0, %1}, %2;" : "=f"(lo), "=f"(hi) : "l"(v));
}
__device__ __forceinline__ void fma2(unsigned long long& d,
                                     unsigned long long a, unsigned long long b) {
    asm("fma.rn.f32x2 %0, %1, %2, %3;" : "=l"(d) : "l"(a), "l"(b), "l"(d));
}

// ---------------- prep: zero cursors + pool ----------------
__global__ void prep_kernel() {
    int i = blockIdx.x * blockDim.x + threadIdx.x;
    int stride = gridDim.x * blockDim.x;
    for (int n = i; n < N_NODES; n += stride) g_deg[n] = 0;
    if (i < N_GRAPHS * D) g_pool[i] = 0.f;
    if (i < N_GRAPHS) g_cnt[i] = 0.f;
}

// ---------------- padded-CSR build: one pass, 4 edges/thread (int4) --------
__global__ __launch_bounds__(256) void place_kernel(const int* __restrict__ ei) {
    int t = blockIdx.x * 256 + threadIdx.x;
    if (t >= N_EDGES / 4) return;
    int4 s4 = __ldg(reinterpret_cast<const int4*>(ei) + t);
    int4 d4 = __ldg(reinterpret_cast<const int4*>(ei + N_EDGES) + t);
    int ss[4] = {s4.x, s4.y, s4.z, s4.w};
    int dd[4] = {d4.x, d4.y, d4.z, d4.w};
    #pragma unroll
    for (int q = 0; q < 4; ++q) {
        unsigned s = (unsigned)ss[q], d = (unsigned)dd[q];
        if (s < (unsigned)N_NODES && d < (unsigned)N_NODES) {
            int pos = atomicAdd(&g_deg[d], 1);
            if (pos < MAXDEG) g_srcs[d * MAXDEG + pos] = (int)s;
        }
    }
}

// ---------------- gather kernel (round-9 exact: at the L2 roofline) --------
__global__ __launch_bounds__(256, 6) void gather_kernel(
    const float* __restrict__ x, int in_sel)
{
    const float* __restrict__ hin = (in_sel < 0) ? x : g_h[in_sel];
    const float4* __restrict__ h4 = reinterpret_cast<const float4*>(hin);
    unsigned t = blockIdx.x * 256u + threadIdx.x;
    if (t >= (unsigned)N_NODES * 16u) return;
    unsigned n = t >> 4;
    unsigned c = t & 15u;

    float4 acc = __ldg(h4 + (size_t)n * 16 + c);   // self term
    int deg = min(__ldg(&g_deg[n]), MAXDEG);
    const int4* __restrict__ sp4 = reinterpret_cast<const int4*>(g_srcs + (size_t)n * MAXDEG);

    int e = 0;
    for (; e + 4 <= deg; e += 4) {
        int4 s = __ldg(sp4 + (e >> 2));
        float4 v0 = __ldg(h4 + (size_t)s.x * 16 + c);
        float4 v1 = __ldg(h4 + (size_t)s.y * 16 + c);
        float4 v2 = __ldg(h4 + (size_t)s.z * 16 + c);
        float4 v3 = __ldg(h4 + (size_t)s.w * 16 + c);
        v0.x += v1.x; v0.y += v1.y; v0.z += v1.z; v0.w += v1.w;
        v2.x += v3.x; v2.y += v3.y; v2.z += v3.z; v2.w += v3.w;
        acc.x += v0.x + v2.x;
        acc.y += v0.y + v2.y;
        acc.z += v0.z + v2.z;
        acc.w += v0.w + v2.w;
    }
    const int* __restrict__ sp = g_srcs + (size_t)n * MAXDEG;
    for (; e < deg; ++e) {
        int s = __ldg(sp + e);
        float4 v = __ldg(h4 + (size_t)s * 16 + c);
        acc.x += v.x; acc.y += v.y; acc.z += v.z; acc.w += v.w;
    }
    reinterpret_cast<float4*>(g_z)[(size_t)n * 16 + c] = acc;
}

// ---------------- MLP kernel: k-split FFMA2, zero packing MOVs --------------
// 512 threads, 128 nodes/block, 2 blocks/SM (32 warps).
// zn[n][k] node-major (pairs over k are natural 8B), Wt[j][k] transposed.
// Thread tile: 4 nodes x 4 outs, outs interleaved {tj, tj+16, tj+32, tj+48}
// (bank-conflict-free Wt loads). acc lanes = even/odd-k partials.
#define ZN_LD 68
#define WT_LD 68
#define MLP_SMEM_FLOATS (NPB * ZN_LD + D * WT_LD + 4 * D)  // 13312 fl = 53248 B

__global__ __launch_bounds__(512, 2) void mlp_kernel(
    int out_sel, int layer,
    const float* __restrict__ W1, const float* __restrict__ b1,
    const float* __restrict__ g1, const float* __restrict__ be1,
    const float* __restrict__ m1, const float* __restrict__ v1,
    const float* __restrict__ W2, const float* __restrict__ b2,
    const float* __restrict__ g2, const float* __restrict__ be2,
    const float* __restrict__ m2, const float* __restrict__ v2)
{
    extern __shared__ float smem[];
    float* zn  = smem;                    // [128][68] node-major activations
    float* Wt  = smem + NPB * ZN_LD;      // [64][68] transposed weights
    float* sc1 = Wt + D * WT_LD;
    float* sh1 = sc1 + D;
    float* sc2 = sh1 + D;
    float* sh2 = sc2 + D;

    const int tid = threadIdx.x;
    const int node0 = blockIdx.x * NPB;
    float* __restrict__ hout = g_h[out_sel];
    const float4* __restrict__ z4 = reinterpret_cast<const float4*>(g_z);

    // stage Wt1 = W1^T + folded BN params
    const float* w1g = W1 + layer * D * D;
    #pragma unroll
    for (int i = tid; i < D * D; i += 512) {
        int k = i >> 6, j = i & 63;
        Wt[j * WT_LD + k] = __ldg(w1g + i);
    }
    if (tid < D) {
        int o = layer * D + tid;
        float s1 = __ldg(g1 + o) * rsqrtf(__ldg(v1 + o) + BN_EPS);
        sc1[tid] = s1;
        sh1[tid] = (__ldg(b1 + o) - __ldg(m1 + o)) * s1 + __ldg(be1 + o);
        float s2 = __ldg(g2 + o) * rsqrtf(__ldg(v2 + o) + BN_EPS);
        sc2[tid] = s2;
        sh2[tid] = (__ldg(b2 + o) - __ldg(m2 + o)) * s2 + __ldg(be2 + o);
    }

    // stage z node-major (coalesced LDG.128, aligned STS.128)
    #pragma unroll
    for (int it = 0; it < (NPB * 16) / 512; ++it) {
        int task = tid + it * 512;
        int nl = task >> 4;
        int c  = task & 15;
        int n  = node0 + nl;
        float4 v = make_float4(0.f, 0.f, 0.f, 0.f);
        if (n < N_NODES) v = __ldg(z4 + (size_t)n * 16 + c);
        *reinterpret_cast<float4*>(zn + nl * ZN_LD + c * 4) = v;
    }
    __syncthreads();

    const int tj = tid & 15;
    const int tn = tid >> 4;      // 0..31
    const int n0 = tn * 4;

    unsigned long long acc[4][4];   // [node i][out p], lanes = even/odd k partials
    #pragma unroll
    for (int i = 0; i < 4; ++i)
        #pragma unroll
        for (int p = 0; p < 4; ++p) acc[i][p] = 0ull;

    // ---- GEMM1: z @ W1 ----
    #pragma unroll 4
    for (int kg = 0; kg < 16; ++kg) {
        int k = kg * 4;
        ulonglong2 wa = *reinterpret_cast<const ulonglong2*>(Wt + (tj     ) * WT_LD + k);
        ulonglong2 wb = *reinterpret_cast<const ulonglong2*>(Wt + (tj + 16) * WT_LD + k);
        ulonglong2 wc = *reinterpret_cast<const ulonglong2*>(Wt + (tj + 32) * WT_LD + k);
        ulonglong2 wd = *reinterpret_cast<const ulonglong2*>(Wt + (tj + 48) * WT_LD + k);
        #pragma unroll
        for (int i = 0; i < 4; ++i) {
            ulonglong2 z = *reinterpret_cast<const ulonglong2*>(zn + (n0 + i) * ZN_LD + k);
            fma2(acc[i][0], z.x, wa.x); fma2(acc[i][0], z.y, wa.y);
            fma2(acc[i][1], z.x, wb.x); fma2(acc[i][1], z.y, wb.y);
            fma2(acc[i][2], z.x, wc.x); fma2(acc[i][2], z.y, wc.y);
            fma2(acc[i][3], z.x, wd.x); fma2(acc[i][3], z.y, wd.y);
        }
    }
    __syncthreads();   // all zn/Wt reads of GEMM1 done

    // BN1 + ReLU -> y back into zn[n][j], j = tj + 16p; stage Wt2
    {
        float s_[4] = {sc1[tj], sc1[tj + 16], sc1[tj + 32], sc1[tj + 48]};
        float t_[4] = {sh1[tj], sh1[tj + 16], sh1[tj + 32], sh1[tj + 48]};
        #pragma unroll
        for (int i = 0; i < 4; ++i)
            #pragma unroll
            for (int p = 0; p < 4; ++p) {
                float lo, hi;
                unpack2(lo, hi, acc[i][p]);
                zn[(n0 + i) * ZN_LD + tj + 16 * p] =
                    fmaxf(fmaf(lo + hi, s_[p], t_[p]), 0.f);
            }
    }
    const float* w2g = W2 + layer * D * D;
    #pragma unroll
    for (int i = tid; i < D * D; i += 512) {
        int k = i >> 6, j = i & 63;
        Wt[j * WT_LD + k] = __ldg(w2g + i);
    }
    __syncthreads();

    // ---- GEMM2: y @ W2 ----
    #pragma unroll
    for (int i = 0; i < 4; ++i)
        #pragma unroll
        for (int p = 0; p < 4; ++p) acc[i][p] = 0ull;

    #pragma unroll 4
    for (int kg = 0; kg < 16; ++kg) {
        int k = kg * 4;
        ulonglong2 wa = *reinterpret_cast<const ulonglong2*>(Wt + (tj     ) * WT_LD + k);
        ulonglong2 wb = *reinterpret_cast<const ulonglong2*>(Wt + (tj + 16) * WT_LD + k);
        ulonglong2 wc = *reinterpret_cast<const ulonglong2*>(Wt + (tj + 32) * WT_LD + k);
        ulonglong2 wd = *reinterpret_cast<const ulonglong2*>(Wt + (tj + 48) * WT_LD + k);
        #pragma unroll
        for (int i = 0; i < 4; ++i) {
            ulonglong2 z = *reinterpret_cast<const ulonglong2*>(zn + (n0 + i) * ZN_LD + k);
            fma2(acc[i][0], z.x, wa.x); fma2(acc[i][0], z.y, wa.y);
            fma2(acc[i][1], z.x, wb.x); fma2(acc[i][1], z.y, wb.y);
            fma2(acc[i][2], z.x, wc.x); fma2(acc[i][2], z.y, wc.y);
            fma2(acc[i][3], z.x, wd.x); fma2(acc[i][3], z.y, wd.y);
        }
    }
    __syncthreads();   // all zn reads of GEMM2 done

    // BN2 + ReLU -> zn[n][j], then coalesced float4 copy to hout
    {
        float s_[4] = {sc2[tj], sc2[tj + 16], sc2[tj + 32], sc2[tj + 48]};
        float t_[4] = {sh2[tj], sh2[tj + 16], sh2[tj + 32], sh2[tj + 48]};
        #pragma unroll
        for (int i = 0; i < 4; ++i)
            #pragma unroll
            for (int p = 0; p < 4; ++p) {
                float lo, hi;
                unpack2(lo, hi, acc[i][p]);
                zn[(n0 + i) * ZN_LD + tj + 16 * p] =
                    fmaxf(fmaf(lo + hi, s_[p], t_[p]), 0.f);
            }
    }
    __syncthreads();

    #pragma unroll
    for (int it = 0; it < (NPB * 16) / 512; ++it) {
        int task = tid + it * 512;
        int nl = task >> 4;
        int c  = task & 15;
        int n  = node0 + nl;
        if (n < N_NODES) {
            float4 v = *reinterpret_cast<const float4*>(zn + nl * ZN_LD + c * 4);
            *reinterpret_cast<float4*>(hout + (size_t)n * D + c * 4) = v;
        }
    }
}

// ---------------- global mean pool (batch is sorted int32) ----------------
#define POOL_BLOCKS 512
__global__ __launch_bounds__(256) void pool_kernel(const int* __restrict__ batch, int sel) {
    const float* __restrict__ h = g_h[sel];
    int d = threadIdx.x & 63;
    int row = blockIdx.x * 4 + (threadIdx.x >> 6);
    int total_rows = POOL_BLOCKS * 4;
    int chunk = (N_NODES + total_rows - 1) / total_rows;
    int start = row * chunk;
    int end = min(start + chunk, N_NODES);
    if (start >= end) return;
    int cur = __ldg(batch + start);
    float acc = 0.f, cnt = 0.f;
    for (int n = start; n < end; ++n) {
        int b = __ldg(batch + n);
        if (b != cur) {
            if ((unsigned)cur < N_GRAPHS) {
                atomicAdd(&g_pool[cur * D + d], acc);
                if (d == 0) atomicAdd(&g_cnt[cur], cnt);
            }
            acc = 0.f; cnt = 0.f; cur = b;
        }
        acc += __ldg(h + (size_t)n * D + d);
        cnt += 1.f;
    }
    if ((unsigned)cur < N_GRAPHS) {
        atomicAdd(&g_pool[cur * D + d], acc);
        if (d == 0) atomicAdd(&g_cnt[cur], cnt);
    }
}

// ---------------- heads: out = [primary(16x6), secondary(16x6)] ----------------
__global__ void head_kernel(const float* __restrict__ wp, const float* __restrict__ bp,
                            const float* __restrict__ ws, const float* __restrict__ bs,
                            float* __restrict__ out) {
    int t = threadIdx.x;
    if (t >= N_GRAPHS * N_CLASSES) return;
    int g = t / N_CLASSES, c = t % N_CLASSES;
    float inv = 1.f / fmaxf(g_cnt[g], 1.f);
    float accP = 0.f, accS = 0.f;
    #pragma unroll
    for (int d = 0; d < D; ++d) {
        float p = g_pool[g * D + d] * inv;
        accP = fmaf(p, wp[d * N_CLASSES + c], accP);
        accS = fmaf(p, ws[d * N_CLASSES + c], accS);
    }
    out[g * N_CLASSES + c] = accP + bp[c];
    out[N_GRAPHS * N_CLASSES + g * N_CLASSES + c] = accS + bs[c];
}

// ---------------- launch ----------------
extern "C" void kernel_launch(void* const* d_in, const int* in_sizes, int n_in,
                              void* d_out, int out_size) {
    const float* x   = (const float*)d_in[0];
    const int*   ei  = (const int*)d_in[1];    // int32 (JAX x64 disabled)
    const int*   bat = (const int*)d_in[2];    // int32
    const float* W1  = (const float*)d_in[3];
    const float* b1  = (const float*)d_in[4];
    const float* g1  = (const float*)d_in[5];
    const float* be1 = (const float*)d_in[6];
    const float* m1  = (const float*)d_in[7];
    const float* v1  = (const float*)d_in[8];
    const float* W2  = (const float*)d_in[9];
    const float* b2  = (const float*)d_in[10];
    const float* g2  = (const float*)d_in[11];
    const float* be2 = (const float*)d_in[12];
    const float* m2  = (const float*)d_in[13];
    const float* v2  = (const float*)d_in[14];
    const float* wp  = (const float*)d_in[15];
    const float* bp  = (const float*)d_in[16];
    const float* ws  = (const float*)d_in[17];
    const float* bs  = (const float*)d_in[18];
    float* out = (float*)d_out;

    const size_t mlp_smem = MLP_SMEM_FLOATS * sizeof(float);  // 53.2 KB
    cudaFuncSetAttribute(mlp_kernel, cudaFuncAttributeMaxDynamicSharedMemorySize,
                         (int)mlp_smem);

    // padded-CSR build (one histogram-free pass)
    prep_kernel<<<512, 256>>>();
    place_kernel<<<(N_EDGES / 4 + 255) / 256, 256>>>(ei);

    const int gather_grid = (N_NODES * 16 + 255) / 256;
    const int mlp_grid = (N_NODES + NPB - 1) / NPB;

    gather_kernel<<<gather_grid, 256>>>(x, -1);
    mlp_kernel<<<mlp_grid, 512, mlp_smem>>>(0, 0,
        W1, b1, g1, be1, m1, v1, W2, b2, g2, be2, m2, v2);
    gather_kernel<<<gather_grid, 256>>>(x, 0);
    mlp_kernel<<<mlp_grid, 512, mlp_smem>>>(1, 1,
        W1, b1, g1, be1, m1, v1, W2, b2, g2, be2, m2, v2);
    gather_kernel<<<gather_grid, 256>>>(x, 1);
    mlp_kernel<<<mlp_grid, 512, mlp_smem>>>(0, 2,
        W1, b1, g1, be1, m1, v1, W2, b2, g2, be2, m2, v2);

    pool_kernel<<<POOL_BLOCKS, 256>>>(bat, 0);
    head_kernel<<<1, 128>>>(wp, bp, ws, bs, out);
}

// round 13
// speedup vs baseline: 1.1767x; 1.1767x over previous
#include <cuda_runtime.h>
#include <cuda_bf16.h>
#include <cstdint>

#define N_NODES 100000
#define N_EDGES 1600000
#define D 64
#define N_GRAPHS 16
#define N_CLASSES 6
#define BN_EPS 1e-5f
#define MAXDEG 64   // Poisson(16): max over 100K nodes ~35; P(any >= 64) < 1e-15

#define NPB 128

// ---------------- device scratch (no allocation allowed) ----------------
__device__ __align__(16) float g_h[2][N_NODES * D];   // ping-pong layer buffers
__device__ __align__(16) float g_z[N_NODES * D];      // gathered z = h + sum h_j
__device__ int g_deg[N_NODES];                        // per-dst degree (atomic cursor)
__device__ __align__(16) int g_srcs[N_NODES * MAXDEG]; // padded CSR (16B-aligned rows)
__device__ float g_pool[N_GRAPHS * D];                // per-graph sums
__device__ float g_cnt[N_GRAPHS];                     // per-graph counts

// ---------------- packed f32x2 helpers (FFMA2: 2x FP32 FMA rate) ----------
__device__ __forceinline__ unsigned long long pack2(float lo, float hi) {
    unsigned long long r;
    asm("mov.b64 %0, {%1, %2};" : "=l"(r) : "f"(lo), "f"(hi));
    return r;
}
__device__ __forceinline__ void unpack2(float& lo, float& hi, unsigned long long v) {
    asm("mov.b64 {%0, %1}, %2;" : "=f"(lo), "=f"(hi) : "l"(v));
}
__device__ __forceinline__ void fma2(unsigned long long& d,
                                     unsigned long long a, unsigned long long b) {
    asm("fma.rn.f32x2 %0, %1, %2, %3;" : "=l"(d) : "l"(a), "l"(b), "l"(d));
}

// ---------------- prep: zero cursors + pool ----------------
__global__ void prep_kernel() {
    int i = blockIdx.x * blockDim.x + threadIdx.x;
    int stride = gridDim.x * blockDim.x;
    for (int n = i; n < N_NODES; n += stride) g_deg[n] = 0;
    if (i < N_GRAPHS * D) g_pool[i] = 0.f;
    if (i < N_GRAPHS) g_cnt[i] = 0.f;
}

// ---------------- padded-CSR build: one pass, 4 edges/thread (int4) --------
__global__ __launch_bounds__(256) void place_kernel(const int* __restrict__ ei) {
    int t = blockIdx.x * 256 + threadIdx.x;
    if (t >= N_EDGES / 4) return;
    int4 s4 = __ldg(reinterpret_cast<const int4*>(ei) + t);
    int4 d4 = __ldg(reinterpret_cast<const int4*>(ei + N_EDGES) + t);
    int ss[4] = {s4.x, s4.y, s4.z, s4.w};
    int dd[4] = {d4.x, d4.y, d4.z, d4.w};
    #pragma unroll
    for (int q = 0; q < 4; ++q) {
        unsigned s = (unsigned)ss[q], d = (unsigned)dd[q];
        if (s < (unsigned)N_NODES && d < (unsigned)N_NODES) {
            int pos = atomicAdd(&g_deg[d], 1);
            if (pos < MAXDEG) g_srcs[d * MAXDEG + pos] = (int)s;
        }
    }
}

// ---------------- gather kernel (round-9 exact: at the L2 roofline) --------
__global__ __launch_bounds__(256, 6) void gather_kernel(
    const float* __restrict__ x, int in_sel)
{
    const float* __restrict__ hin = (in_sel < 0) ? x : g_h[in_sel];
    const float4* __restrict__ h4 = reinterpret_cast<const float4*>(hin);
    unsigned t = blockIdx.x * 256u + threadIdx.x;
    if (t >= (unsigned)N_NODES * 16u) return;
    unsigned n = t >> 4;
    unsigned c = t & 15u;

    float4 acc = __ldg(h4 + (size_t)n * 16 + c);   // self term
    int deg = min(__ldg(&g_deg[n]), MAXDEG);
    const int4* __restrict__ sp4 = reinterpret_cast<const int4*>(g_srcs + (size_t)n * MAXDEG);

    int e = 0;
    for (; e + 4 <= deg; e += 4) {
        int4 s = __ldg(sp4 + (e >> 2));
        float4 v0 = __ldg(h4 + (size_t)s.x * 16 + c);
        float4 v1 = __ldg(h4 + (size_t)s.y * 16 + c);
        float4 v2 = __ldg(h4 + (size_t)s.z * 16 + c);
        float4 v3 = __ldg(h4 + (size_t)s.w * 16 + c);
        v0.x += v1.x; v0.y += v1.y; v0.z += v1.z; v0.w += v1.w;
        v2.x += v3.x; v2.y += v3.y; v2.z += v3.z; v2.w += v3.w;
        acc.x += v0.x + v2.x;
        acc.y += v0.y + v2.y;
        acc.z += v0.z + v2.z;
        acc.w += v0.w + v2.w;
    }
    const int* __restrict__ sp = g_srcs + (size_t)n * MAXDEG;
    for (; e < deg; ++e) {
        int s = __ldg(sp + e);
        float4 v = __ldg(h4 + (size_t)s * 16 + c);
        acc.x += v.x; acc.y += v.y; acc.z += v.z; acc.w += v.w;
    }
    reinterpret_cast<float4*>(g_z)[(size_t)n * 16 + c] = acc;
}

// ---------------- MLP kernel: h' = relu(bn2(relu(bn1(z@W1))@W2)) ------------
// Round-9 structure; launch_bounds(256,3) -> 84-reg cap so the unroll-4
// software pipeline (48 load regs + 32 acc) fits without clamping. 3 blocks/SM.
#define ZT_LD 132
#define MLP_SMEM_FLOATS (D * ZT_LD + D * D + 4 * D)  // 12800 floats = 51.2KB

__global__ __launch_bounds__(256, 3) void mlp_kernel(
    int out_sel, int layer,
    const float* __restrict__ W1, const float* __restrict__ b1,
    const float* __restrict__ g1, const float* __restrict__ be1,
    const float* __restrict__ m1, const float* __restrict__ v1,
    const float* __restrict__ W2, const float* __restrict__ b2,
    const float* __restrict__ g2, const float* __restrict__ be2,
    const float* __restrict__ m2, const float* __restrict__ v2)
{
    extern __shared__ float smem[];
    float* zt  = smem;                    // [64][132] transposed activations
    float* Wb  = smem + D * ZT_LD;        // [64][64] current weight
    float* sc1 = Wb + D * D;
    float* sh1 = sc1 + D;
    float* sc2 = sh1 + D;
    float* sh2 = sc2 + D;

    const int tid = threadIdx.x;
    const int node0 = blockIdx.x * NPB;
    float* __restrict__ hout = g_h[out_sel];
    const float4* __restrict__ z4 = reinterpret_cast<const float4*>(g_z);

    // stage W1 + folded BN params
    const float* w1 = W1 + layer * D * D;
    #pragma unroll
    for (int i = tid; i < D * D; i += 256) Wb[i] = __ldg(w1 + i);
    if (tid < D) {
        int o = layer * D + tid;
        float s1 = __ldg(g1 + o) * rsqrtf(__ldg(v1 + o) + BN_EPS);
        sc1[tid] = s1;
        sh1[tid] = (__ldg(b1 + o) - __ldg(m1 + o)) * s1 + __ldg(be1 + o);
        float s2 = __ldg(g2 + o) * rsqrtf(__ldg(v2 + o) + BN_EPS);
        sc2[tid] = s2;
        sh2[tid] = (__ldg(b2 + o) - __ldg(m2 + o)) * s2 + __ldg(be2 + o);
    }

    // stage z transposed: task = (local node, chunk)
    #pragma unroll
    for (int it = 0; it < (NPB * 16) / 256; ++it) {
        int task = tid + it * 256;
        int nl = task >> 4;
        int c  = task & 15;
        int n  = node0 + nl;
        if (n < N_NODES) {
            float4 v = __ldg(z4 + (size_t)n * 16 + c);
            int k = c * 4;
            zt[(k + 0) * ZT_LD + nl] = v.x;
            zt[(k + 1) * ZT_LD + nl] = v.y;
            zt[(k + 2) * ZT_LD + nl] = v.z;
            zt[(k + 3) * ZT_LD + nl] = v.w;
        }
    }
    __syncthreads();

    // ---- GEMM thread tile: 8 nodes (4 f32x2 pairs) x 4 outs ----
    const int tj = tid & 15;
    const int tn = tid >> 4;
    const int j0 = tj * 4;
    const int n0 = tn * 8;

    unsigned long long acc[4][4];
    #pragma unroll
    for (int p = 0; p < 4; ++p)
        #pragma unroll
        for (int j = 0; j < 4; ++j) acc[p][j] = 0ull;

    // GEMM1: z @ W1
    #pragma unroll 4
    for (int k = 0; k < D; ++k) {
        ulonglong2 za = *reinterpret_cast<const ulonglong2*>(zt + k * ZT_LD + n0);
        ulonglong2 zb = *reinterpret_cast<const ulonglong2*>(zt + k * ZT_LD + n0 + 4);
        float4 w = *reinterpret_cast<const float4*>(Wb + k * D + j0);
        unsigned long long wd0 = pack2(w.x, w.x), wd1 = pack2(w.y, w.y);
        unsigned long long wd2 = pack2(w.z, w.z), wd3 = pack2(w.w, w.w);
        fma2(acc[0][0], za.x, wd0); fma2(acc[0][1], za.x, wd1);
        fma2(acc[0][2], za.x, wd2); fma2(acc[0][3], za.x, wd3);
        fma2(acc[1][0], za.y, wd0); fma2(acc[1][1], za.y, wd1);
        fma2(acc[1][2], za.y, wd2); fma2(acc[1][3], za.y, wd3);
        fma2(acc[2][0], zb.x, wd0); fma2(acc[2][1], zb.x, wd1);
        fma2(acc[2][2], zb.x, wd2); fma2(acc[2][3], zb.x, wd3);
        fma2(acc[3][0], zb.y, wd0); fma2(acc[3][1], zb.y, wd1);
        fma2(acc[3][2], zb.y, wd2); fma2(acc[3][3], zb.y, wd3);
    }
    __syncthreads();

    // BN1 + ReLU -> y back into zt (packed 8B stores); swap W2 into Wb
    {
        float s_[4] = {sc1[j0], sc1[j0 + 1], sc1[j0 + 2], sc1[j0 + 3]};
        float t_[4] = {sh1[j0], sh1[j0 + 1], sh1[j0 + 2], sh1[j0 + 3]};
        #pragma unroll
        for (int p = 0; p < 4; ++p)
            #pragma unroll
            for (int j = 0; j < 4; ++j) {
                float lo, hi;
                unpack2(lo, hi, acc[p][j]);
                lo = fmaxf(fmaf(lo, s_[j], t_[j]), 0.f);
                hi = fmaxf(fmaf(hi, s_[j], t_[j]), 0.f);
                *reinterpret_cast<unsigned long long*>(
                    zt + (j0 + j) * ZT_LD + n0 + 2 * p) = pack2(lo, hi);
            }
    }
    const float* w2 = W2 + layer * D * D;
    #pragma unroll
    for (int i = tid; i < D * D; i += 256) Wb[i] = __ldg(w2 + i);
    __syncthreads();

    // GEMM2: y @ W2
    #pragma unroll
    for (int p = 0; p < 4; ++p)
        #pragma unroll
        for (int j = 0; j < 4; ++j) acc[p][j] = 0ull;

    #pragma unroll 4
    for (int k = 0; k < D; ++k) {
        ulonglong2 ya = *reinterpret_cast<const ulonglong2*>(zt + k * ZT_LD + n0);
        ulonglong2 yb = *reinterpret_cast<const ulonglong2*>(zt + k * ZT_LD + n0 + 4);
        float4 w = *reinterpret_cast<const float4*>(Wb + k * D + j0);
        unsigned long long wd0 = pack2(w.x, w.x), wd1 = pack2(w.y, w.y);
        unsigned long long wd2 = pack2(w.z, w.z), wd3 = pack2(w.w, w.w);
        fma2(acc[0][0], ya.x, wd0); fma2(acc[0][1], ya.x, wd1);
        fma2(acc[0][2], ya.x, wd2); fma2(acc[0][3], ya.x, wd3);
        fma2(acc[1][0], ya.y, wd0); fma2(acc[1][1], ya.y, wd1);
        fma2(acc[1][2], ya.y, wd2); fma2(acc[1][3], ya.y, wd3);
        fma2(acc[2][0], yb.x, wd0); fma2(acc[2][1], yb.x, wd1);
        fma2(acc[2][2], yb.x, wd2); fma2(acc[2][3], yb.x, wd3);
        fma2(acc[3][0], yb.y, wd0); fma2(acc[3][1], yb.y, wd1);
        fma2(acc[3][2], yb.y, wd2); fma2(acc[3][3], yb.y, wd3);
    }

    // BN2 + ReLU, coalesced vector store (two nodes per pair)
    {
        float s_[4] = {sc2[j0], sc2[j0 + 1], sc2[j0 + 2], sc2[j0 + 3]};
        float t_[4] = {sh2[j0], sh2[j0 + 1], sh2[j0 + 2], sh2[j0 + 3]};
        #pragma unroll
        for (int p = 0; p < 4; ++p) {
            float lo[4], hi[4];
            #pragma unroll
            for (int j = 0; j < 4; ++j) {
                float a, b;
                unpack2(a, b, acc[p][j]);
                lo[j] = fmaxf(fmaf(a, s_[j], t_[j]), 0.f);
                hi[j] = fmaxf(fmaf(b, s_[j], t_[j]), 0.f);
            }
            int na = node0 + n0 + 2 * p;
            int nb = na + 1;
            if (na < N_NODES)
                *reinterpret_cast<float4*>(hout + (size_t)na * D + j0) =
                    make_float4(lo[0], lo[1], lo[2], lo[3]);
            if (nb < N_NODES)
                *reinterpret_cast<float4*>(hout + (size_t)nb * D + j0) =
                    make_float4(hi[0], hi[1], hi[2], hi[3]);
        }
    }
}

// ---------------- global mean pool (batch is sorted int32) ----------------
#define POOL_BLOCKS 512
__global__ __launch_bounds__(256) void pool_kernel(const int* __restrict__ batch, int sel) {
    const float* __restrict__ h = g_h[sel];
    int d = threadIdx.x & 63;
    int row = blockIdx.x * 4 + (threadIdx.x >> 6);
    int total_rows = POOL_BLOCKS * 4;
    int chunk = (N_NODES + total_rows - 1) / total_rows;
    int start = row * chunk;
    int end = min(start + chunk, N_NODES);
    if (start >= end) return;
    int cur = __ldg(batch + start);
    float acc = 0.f, cnt = 0.f;
    for (int n = start; n < end; ++n) {
        int b = __ldg(batch + n);
        if (b != cur) {
            if ((unsigned)cur < N_GRAPHS) {
                atomicAdd(&g_pool[cur * D + d], acc);
                if (d == 0) atomicAdd(&g_cnt[cur], cnt);
            }
            acc = 0.f; cnt = 0.f; cur = b;
        }
        acc += __ldg(h + (size_t)n * D + d);
        cnt += 1.f;
    }
    if ((unsigned)cur < N_GRAPHS) {
        atomicAdd(&g_pool[cur * D + d], acc);
        if (d == 0) atomicAdd(&g_cnt[cur], cnt);
    }
}

// ---------------- heads: out = [primary(16x6), secondary(16x6)] ----------------
__global__ void head_kernel(const float* __restrict__ wp, const float* __restrict__ bp,
                            const float* __restrict__ ws, const float* __restrict__ bs,
                            float* __restrict__ out) {
    int t = threadIdx.x;
    if (t >= N_GRAPHS * N_CLASSES) return;
    int g = t / N_CLASSES, c = t % N_CLASSES;
    float inv = 1.f / fmaxf(g_cnt[g], 1.f);
    float accP = 0.f, accS = 0.f;
    #pragma unroll
    for (int d = 0; d < D; ++d) {
        float p = g_pool[g * D + d] * inv;
        accP = fmaf(p, wp[d * N_CLASSES + c], accP);
        accS = fmaf(p, ws[d * N_CLASSES + c], accS);
    }
    out[g * N_CLASSES + c] = accP + bp[c];
    out[N_GRAPHS * N_CLASSES + g * N_CLASSES + c] = accS + bs[c];
}

// ---------------- launch ----------------
extern "C" void kernel_launch(void* const* d_in, const int* in_sizes, int n_in,
                              void* d_out, int out_size) {
    const float* x   = (const float*)d_in[0];
    const int*   ei  = (const int*)d_in[1];    // int32 (JAX x64 disabled)
    const int*   bat = (const int*)d_in[2];    // int32
    const float* W1  = (const float*)d_in[3];
    const float* b1  = (const float*)d_in[4];
    const float* g1  = (const float*)d_in[5];
    const float* be1 = (const float*)d_in[6];
    const float* m1  = (const float*)d_in[7];
    const float* v1  = (const float*)d_in[8];
    const float* W2  = (const float*)d_in[9];
    const float* b2  = (const float*)d_in[10];
    const float* g2  = (const float*)d_in[11];
    const float* be2 = (const float*)d_in[12];
    const float* m2  = (const float*)d_in[13];
    const float* v2  = (const float*)d_in[14];
    const float* wp  = (const float*)d_in[15];
    const float* bp  = (const float*)d_in[16];
    const float* ws  = (const float*)d_in[17];
    const float* bs  = (const float*)d_in[18];
    float* out = (float*)d_out;

    const size_t mlp_smem = MLP_SMEM_FLOATS * sizeof(float);  // 51.2 KB
    cudaFuncSetAttribute(mlp_kernel, cudaFuncAttributeMaxDynamicSharedMemorySize,
                         (int)mlp_smem);

    // padded-CSR build (one histogram-free pass)
    prep_kernel<<<512, 256>>>();
    place_kernel<<<(N_EDGES / 4 + 255) / 256, 256>>>(ei);

    const int gather_grid = (N_NODES * 16 + 255) / 256;
    const int mlp_grid = (N_NODES + NPB - 1) / NPB;

    gather_kernel<<<gather_grid, 256>>>(x, -1);
    mlp_kernel<<<mlp_grid, 256, mlp_smem>>>(0, 0,
        W1, b1, g1, be1, m1, v1, W2, b2, g2, be2, m2, v2);
    gather_kernel<<<gather_grid, 256>>>(x, 0);
    mlp_kernel<<<mlp_grid, 256, mlp_smem>>>(1, 1,
        W1, b1, g1, be1, m1, v1, W2, b2, g2, be2, m2, v2);
    gather_kernel<<<gather_grid, 256>>>(x, 1);
    mlp_kernel<<<mlp_grid, 256, mlp_smem>>>(0, 2,
        W1, b1, g1, be1, m1, v1, W2, b2, g2, be2, m2, v2);

    pool_kernel<<<POOL_BLOCKS, 256>>>(bat, 0);
    head_kernel<<<1, 128>>>(wp, bp, ws, bs, out);
}